// round 14
// baseline (speedup 1.0000x reference)
#include <cuda_runtime.h>

// quadLayer: out[b,h,w, c*512 + a*32 + f] =
//   sum_m p[a][m] W1[c][m][f] + sum_{m1,m2} p[a][m1] p[a][m2] W2[c][m1*4+m2][f]
// p[a][mm] = x[b, 2h+((a>>2)>>1), 2w+((a>>2)&1), 4*(a&3)+mm]  (one float4 of x).
//
// R14 = R13 inner loop (Horner symmetric quadratic, a-parity-packed smem,
// 1-deep LDS prefetch, serialized planes, .cs stores) made PERSISTENT:
// 456 CTAs (3 x 152 SMs), each owns 17-18 contiguous pixels -> wave-
// quantization loss drops from 8.4% to ~0.3%; weight prologue amortized
// over the whole run; per-pixel build double-buffered with 1 sync/pixel.

#define THREADS 256
#define NCTA 456          // 3 CTAs/SM x 152 SMs (GB300)
// 8192 pixels = 440*18 + 16*17

__device__ __forceinline__ unsigned long long pack2(float lo, float hi) {
    unsigned long long r;
    asm("mov.b64 %0, {%1,%2};" : "=l"(r) : "f"(lo), "f"(hi));
    return r;
}

__device__ __forceinline__ void fma2(unsigned long long &d,
                                     unsigned long long a,
                                     unsigned long long b) {
    asm("fma.rn.f32x2 %0, %1, %2, %0;" : "+l"(d) : "l"(a), "l"(b));
}

__device__ __forceinline__ unsigned long long fma2n(unsigned long long a,
                                                    unsigned long long b,
                                                    unsigned long long c) {
    unsigned long long d;
    asm("fma.rn.f32x2 %0, %1, %2, %3;" : "=l"(d) : "l"(a), "l"(b), "l"(c));
    return d;
}

__device__ __forceinline__ unsigned long long mul2(unsigned long long a,
                                                   unsigned long long b) {
    unsigned long long d;
    asm("mul.rn.f32x2 %0, %1, %2;" : "=l"(d) : "l"(a), "l"(b));
    return d;
}

__device__ __forceinline__ unsigned long long add2(unsigned long long a,
                                                   unsigned long long b) {
    unsigned long long r;
    asm("add.rn.f32x2 %0, %1, %2;" : "=l"(r) : "l"(a), "l"(b));
    return r;
}

__device__ __forceinline__ void store2(float* p, unsigned long long s) {
    float lo, hi;
    asm("mov.b64 {%0,%1}, %2;" : "=f"(lo), "=f"(hi) : "l"(s));
    asm("st.global.cs.f32 [%0], %1;" :: "l"(p),      "f"(lo) : "memory");
    asm("st.global.cs.f32 [%0], %1;" :: "l"(p + 32), "f"(hi) : "memory");
}

// one plane of the Horner lattice
__device__ __forceinline__ unsigned long long plane_eval(
    unsigned long long pp0, unsigned long long pp1,
    unsigned long long pp2, unsigned long long pp3,
    const unsigned long long* __restrict__ lin,
    const unsigned long long* __restrict__ q)
{
    // q idx: (0,0)=0 (0,1)=1 (0,2)=2 (0,3)=3 (1,1)=4 (1,2)=5 (1,3)=6
    //        (2,2)=7 (2,3)=8 (3,3)=9
    unsigned long long t0 = fma2n(pp0, q[0], lin[0]);
    unsigned long long t1 = fma2n(pp1, q[4], lin[1]);
    unsigned long long t2 = fma2n(pp2, q[7], lin[2]);
    unsigned long long t3 = fma2n(pp3, q[9], lin[3]);
    fma2(t0, pp1, q[1]);
    fma2(t1, pp2, q[5]);
    fma2(t2, pp3, q[8]);
    fma2(t0, pp2, q[2]);
    fma2(t1, pp3, q[6]);
    fma2(t0, pp3, q[3]);
    unsigned long long s0 = mul2(pp0, t0);
    unsigned long long s1 = mul2(pp1, t1);
    fma2(s0, pp2, t2);
    fma2(s1, pp3, t3);
    return add2(s0, s1);
}

// build one pixel's base values into a 72-float buffer (a-parity layout)
__device__ __forceinline__ void build_pix(const float* __restrict__ x,
                                          int g, float* __restrict__ fbase,
                                          int t)
{
    if (t < 16) {
        const int a   = t;
        const int b   = g >> 10;
        const int h   = (g >> 5) & 31;
        const int wc  = g & 31;
        const int m   = a >> 2;
        const int i   = m >> 1;
        const int j   = m & 1;
        const int ch0 = (a & 3) * 4;
        const float4 v = *reinterpret_cast<const float4*>(
            x + (((b * 64 + 2 * h + i) * 64) + (2 * wc + j)) * 16 + ch0);
        float* fb = fbase + (a >> 1) * 8 + (a & 1);
        fb[0] = v.x; fb[2] = v.y; fb[4] = v.z; fb[6] = v.w;
    }
}

__global__ void __launch_bounds__(THREADS, 3)
quad_kernel(const float* __restrict__ x,
            const float* __restrict__ W1,
            const float* __restrict__ W2,
            float* __restrict__ out)
{
    // two per-pixel buffers: 8 ap * 4 m * 2 parity = 64 floats + 8 pad (over-prefetch)
    __shared__ __align__(16) float buf[2][72];

    const int t  = threadIdx.x;
    const int c0 = t >> 5;   // 0..7  (planes c0 and c0+8)
    const int f  = t & 31;   // 0..31

    // ---- weights (duplicated f32x2), Horner layout — once per CTA ----
    unsigned long long linA[4], linB[4], qA[10], qB[10];
    {
        const float* w1a = W1 + c0 * 128 + f;
        const float* w1b = W1 + (c0 + 8) * 128 + f;
        const float* w2a = W2 + c0 * 512 + f;
        const float* w2b = W2 + (c0 + 8) * 512 + f;
#pragma unroll
        for (int m = 0; m < 4; m++) {
            float a = w1a[m * 32], b = w1b[m * 32];
            linA[m] = pack2(a, a);
            linB[m] = pack2(b, b);
        }
        int k = 0;
#pragma unroll
        for (int m1 = 0; m1 < 4; m1++)
#pragma unroll
            for (int m2 = m1; m2 < 4; m2++) {
                float a, b;
                if (m1 == m2) {
                    a = w2a[(5 * m1) * 32];
                    b = w2b[(5 * m1) * 32];
                } else {
                    a = w2a[(m1 * 4 + m2) * 32] + w2a[(m2 * 4 + m1) * 32];
                    b = w2b[(m1 * 4 + m2) * 32] + w2b[(m2 * 4 + m1) * 32];
                }
                qA[k] = pack2(a, a);
                qB[k] = pack2(b, b);
                k++;
            }
    }

    // ---- pixel range for this CTA: 440 CTAs x 18 + 16 CTAs x 17 = 8192 ----
    const int bid   = blockIdx.x;
    const int start = (bid < 440) ? bid * 18 : 440 * 18 + (bid - 440) * 17;
    const int count = (bid < 440) ? 18 : 17;

    build_pix(x, start, &buf[0][0], t);
    __syncthreads();

#pragma unroll 1
    for (int i = 0; i < count; i++) {
        const int g = start + i;
        if (i + 1 < count)
            build_pix(x, g + 1, &buf[(i + 1) & 1][0], t);

        float* outA = out + (size_t)g * 8192 + (size_t)(c0 * 512 + f);
        float* outB = outA + 4096;
        unsigned int saddr =
            (unsigned int)__cvta_generic_to_shared(&buf[i & 1][0]);

        // prime the 1-deep pipeline
        unsigned long long p0, p1, p2, p3;
        asm("ld.shared.v2.u64 {%0,%1}, [%2];" : "=l"(p0), "=l"(p1) : "r"(saddr));
        asm("ld.shared.v2.u64 {%0,%1}, [%2];" : "=l"(p2), "=l"(p3) : "r"(saddr + 16));
        saddr += 32;

#pragma unroll
        for (int ap = 0; ap < 8; ap++) {
            unsigned long long n0, n1, n2, n3;   // pad covers the last over-read
            asm("ld.shared.v2.u64 {%0,%1}, [%2];"
                : "=l"(n0), "=l"(n1) : "r"(saddr));
            asm("ld.shared.v2.u64 {%0,%1}, [%2];"
                : "=l"(n2), "=l"(n3) : "r"(saddr + 16));
            saddr += 32;

            store2(outA + (2 * ap) * 32, plane_eval(p0, p1, p2, p3, linA, qA));
            store2(outB + (2 * ap) * 32, plane_eval(p0, p1, p2, p3, linB, qB));

            p0 = n0; p1 = n1; p2 = n2; p3 = n3;
        }
        __syncthreads();   // build(i+1) visible; buf[i&1] free for rebuild at i+2
    }
}

extern "C" void kernel_launch(void* const* d_in, const int* in_sizes, int n_in,
                              void* d_out, int out_size) {
    const float* x  = (const float*)d_in[0];
    const float* W1 = (const float*)d_in[1];
    const float* W2 = (const float*)d_in[2];
    float* out = (float*)d_out;
    quad_kernel<<<NCTA, THREADS>>>(x, W1, W2, out);
}

// round 15
// speedup vs baseline: 1.0974x; 1.0974x over previous
#include <cuda_runtime.h>

// quadLayer: out[b,h,w, c*512 + a*32 + f] =
//   sum_m p[a][m] W1[c][m][f] + sum_{m1,m2} p[a][m1] p[a][m2] W2[c][m1*4+m2][f]
// p[a][mm] = x[b, 2h+((a>>2)>>1), 2w+((a>>2)&1), 4*(a&3)+mm]  (one float4 of x).
//
// R15 = persistent 456-CTA split (R14) + ONE-SHOT base build: all 17-18
// pixels' base values staged into contiguous smem up front, ONE sync, then
// R13's prefetched Horner loop streams sync-free across all pixels.
// (R14's per-pixel __syncthreads was the regression source.)

#define THREADS 256
#define NCTA 456          // 3 CTAs/SM x 152 SMs (GB300)
#define MAXPIX 18         // 8192 = 440*18 + 16*17

__device__ __forceinline__ unsigned long long pack2(float lo, float hi) {
    unsigned long long r;
    asm("mov.b64 %0, {%1,%2};" : "=l"(r) : "f"(lo), "f"(hi));
    return r;
}

__device__ __forceinline__ void fma2(unsigned long long &d,
                                     unsigned long long a,
                                     unsigned long long b) {
    asm("fma.rn.f32x2 %0, %1, %2, %0;" : "+l"(d) : "l"(a), "l"(b));
}

__device__ __forceinline__ unsigned long long fma2n(unsigned long long a,
                                                    unsigned long long b,
                                                    unsigned long long c) {
    unsigned long long d;
    asm("fma.rn.f32x2 %0, %1, %2, %3;" : "=l"(d) : "l"(a), "l"(b), "l"(c));
    return d;
}

__device__ __forceinline__ unsigned long long mul2(unsigned long long a,
                                                   unsigned long long b) {
    unsigned long long d;
    asm("mul.rn.f32x2 %0, %1, %2;" : "=l"(d) : "l"(a), "l"(b));
    return d;
}

__device__ __forceinline__ unsigned long long add2(unsigned long long a,
                                                   unsigned long long b) {
    unsigned long long r;
    asm("add.rn.f32x2 %0, %1, %2;" : "=l"(r) : "l"(a), "l"(b));
    return r;
}

__device__ __forceinline__ void store2(float* p, unsigned long long s) {
    float lo, hi;
    asm("mov.b64 {%0,%1}, %2;" : "=f"(lo), "=f"(hi) : "l"(s));
    asm("st.global.cs.f32 [%0], %1;" :: "l"(p),      "f"(lo) : "memory");
    asm("st.global.cs.f32 [%0], %1;" :: "l"(p + 32), "f"(hi) : "memory");
}

// one plane of the Horner lattice
__device__ __forceinline__ unsigned long long plane_eval(
    unsigned long long pp0, unsigned long long pp1,
    unsigned long long pp2, unsigned long long pp3,
    const unsigned long long* __restrict__ lin,
    const unsigned long long* __restrict__ q)
{
    // q idx: (0,0)=0 (0,1)=1 (0,2)=2 (0,3)=3 (1,1)=4 (1,2)=5 (1,3)=6
    //        (2,2)=7 (2,3)=8 (3,3)=9
    unsigned long long t0 = fma2n(pp0, q[0], lin[0]);
    unsigned long long t1 = fma2n(pp1, q[4], lin[1]);
    unsigned long long t2 = fma2n(pp2, q[7], lin[2]);
    unsigned long long t3 = fma2n(pp3, q[9], lin[3]);
    fma2(t0, pp1, q[1]);
    fma2(t1, pp2, q[5]);
    fma2(t2, pp3, q[8]);
    fma2(t0, pp2, q[2]);
    fma2(t1, pp3, q[6]);
    fma2(t0, pp3, q[3]);
    unsigned long long s0 = mul2(pp0, t0);
    unsigned long long s1 = mul2(pp1, t1);
    fma2(s0, pp2, t2);
    fma2(s1, pp3, t3);
    return add2(s0, s1);
}

__global__ void __launch_bounds__(THREADS, 3)
quad_kernel(const float* __restrict__ x,
            const float* __restrict__ W1,
            const float* __restrict__ W2,
            float* __restrict__ out)
{
    // all pixels' base values, contiguous: MAXPIX * 64 floats + 8 pad = 4.6 KB
    __shared__ __align__(16) float pbase[MAXPIX * 64 + 8];

    const int t  = threadIdx.x;
    const int c0 = t >> 5;   // 0..7  (planes c0 and c0+8)
    const int f  = t & 31;   // 0..31

    // ---- weights (duplicated f32x2), Horner layout — once per CTA ----
    unsigned long long linA[4], linB[4], qA[10], qB[10];
    {
        const float* w1a = W1 + c0 * 128 + f;
        const float* w1b = W1 + (c0 + 8) * 128 + f;
        const float* w2a = W2 + c0 * 512 + f;
        const float* w2b = W2 + (c0 + 8) * 512 + f;
#pragma unroll
        for (int m = 0; m < 4; m++) {
            float a = w1a[m * 32], b = w1b[m * 32];
            linA[m] = pack2(a, a);
            linB[m] = pack2(b, b);
        }
        int k = 0;
#pragma unroll
        for (int m1 = 0; m1 < 4; m1++)
#pragma unroll
            for (int m2 = m1; m2 < 4; m2++) {
                float a, b;
                if (m1 == m2) {
                    a = w2a[(5 * m1) * 32];
                    b = w2b[(5 * m1) * 32];
                } else {
                    a = w2a[(m1 * 4 + m2) * 32] + w2a[(m2 * 4 + m1) * 32];
                    b = w2b[(m1 * 4 + m2) * 32] + w2b[(m2 * 4 + m1) * 32];
                }
                qA[k] = pack2(a, a);
                qB[k] = pack2(b, b);
                k++;
            }
    }

    // ---- pixel range: 440 CTAs x 18 + 16 CTAs x 17 = 8192 ----
    const int bid   = blockIdx.x;
    const int start = (bid < 440) ? bid * 18 : 440 * 18 + (bid - 440) * 17;
    const int count = (bid < 440) ? 18 : 17;

    // ---- one-shot build of ALL pixels' base values ----
    for (int idx = t; idx < count * 16; idx += THREADS) {
        const int pix = idx >> 4;
        const int a   = idx & 15;
        const int g   = start + pix;
        const int b   = g >> 10;
        const int h   = (g >> 5) & 31;
        const int wc  = g & 31;
        const int m   = a >> 2;
        const int i   = m >> 1;
        const int j   = m & 1;
        const int ch0 = (a & 3) * 4;
        const float4 v = *reinterpret_cast<const float4*>(
            x + (((b * 64 + 2 * h + i) * 64) + (2 * wc + j)) * 16 + ch0);
        float* fb = &pbase[pix * 64 + (a >> 1) * 8 + (a & 1)];
        fb[0] = v.x; fb[2] = v.y; fb[4] = v.z; fb[6] = v.w;
    }
    __syncthreads();   // the ONLY barrier

    float* outA = out + (size_t)start * 8192 + (size_t)(c0 * 512 + f);
    float* outB = outA + 4096;
    unsigned int saddr = (unsigned int)__cvta_generic_to_shared(pbase);

    // prime the 1-deep pipeline (contiguous across all pixels)
    unsigned long long p0, p1, p2, p3;
    asm("ld.shared.v2.u64 {%0,%1}, [%2];" : "=l"(p0), "=l"(p1) : "r"(saddr));
    asm("ld.shared.v2.u64 {%0,%1}, [%2];" : "=l"(p2), "=l"(p3) : "r"(saddr + 16));
    saddr += 32;

#pragma unroll 1
    for (int i = 0; i < count; i++) {
#pragma unroll
        for (int ap = 0; ap < 8; ap++) {
            unsigned long long n0, n1, n2, n3;   // pad covers final over-read
            asm("ld.shared.v2.u64 {%0,%1}, [%2];"
                : "=l"(n0), "=l"(n1) : "r"(saddr));
            asm("ld.shared.v2.u64 {%0,%1}, [%2];"
                : "=l"(n2), "=l"(n3) : "r"(saddr + 16));
            saddr += 32;

            store2(outA + (2 * ap) * 32, plane_eval(p0, p1, p2, p3, linA, qA));
            store2(outB + (2 * ap) * 32, plane_eval(p0, p1, p2, p3, linB, qB));

            p0 = n0; p1 = n1; p2 = n2; p3 = n3;
        }
        outA += 8192;
        outB += 8192;
    }
}

extern "C" void kernel_launch(void* const* d_in, const int* in_sizes, int n_in,
                              void* d_out, int out_size) {
    const float* x  = (const float*)d_in[0];
    const float* W1 = (const float*)d_in[1];
    const float* W2 = (const float*)d_in[2];
    float* out = (float*)d_out;
    quad_kernel<<<NCTA, THREADS>>>(x, W1, W2, out);
}